// round 6
// baseline (speedup 1.0000x reference)
#include <cuda_runtime.h>
#include <cstdint>

#define VOCAB 50000
#define EDIM  256
#define HDIM  256
#define BATCH 64
#define TLEN  2048

typedef unsigned long long u64;

// proj_table[v][h] = sum_e emb[v][e] * W_ih[h][e]   (51.2 MB device scratch)
__device__ float g_proj[VOCAB * HDIM];

// ---------------------------------------------------------------------------
// Kernel A: proj = emb @ W_ih^T   (NT SGEMM, C[50000,256])  -- unchanged
// ---------------------------------------------------------------------------
__global__ __launch_bounds__(256) void proj_kernel(const float* __restrict__ emb,
                                                   const float* __restrict__ Wih) {
    __shared__ float As[32][128];
    __shared__ float Bs[32][128];

    const int n0 = blockIdx.x * 128;
    const int m0 = blockIdx.y * 128;
    const int tid = threadIdx.x;
    const int tx = tid & 15;
    const int ty = tid >> 4;

    float acc[8][8];
#pragma unroll
    for (int a = 0; a < 8; a++)
#pragma unroll
        for (int bb = 0; bb < 8; bb++) acc[a][bb] = 0.0f;

    for (int kc = 0; kc < EDIM; kc += 32) {
#pragma unroll
        for (int q = 0; q < 4; q++) {
            int fid = tid + 256 * q;
            int row = fid >> 3;
            int col = fid & 7;
            float4 av = make_float4(0.f, 0.f, 0.f, 0.f);
            int m = m0 + row;
            if (m < VOCAB)
                av = __ldg((const float4*)(emb + (size_t)m * EDIM + kc + col * 4));
            As[col * 4 + 0][row] = av.x;
            As[col * 4 + 1][row] = av.y;
            As[col * 4 + 2][row] = av.z;
            As[col * 4 + 3][row] = av.w;
            float4 bv = __ldg((const float4*)(Wih + (size_t)(n0 + row) * EDIM + kc + col * 4));
            Bs[col * 4 + 0][row] = bv.x;
            Bs[col * 4 + 1][row] = bv.y;
            Bs[col * 4 + 2][row] = bv.z;
            Bs[col * 4 + 3][row] = bv.w;
        }
        __syncthreads();

#pragma unroll
        for (int k = 0; k < 32; k++) {
            float a[8], b[8];
            *(float4*)&a[0] = *(const float4*)&As[k][ty * 8];
            *(float4*)&a[4] = *(const float4*)&As[k][ty * 8 + 4];
            *(float4*)&b[0] = *(const float4*)&Bs[k][tx * 8];
            *(float4*)&b[4] = *(const float4*)&Bs[k][tx * 8 + 4];
#pragma unroll
            for (int ii = 0; ii < 8; ii++)
#pragma unroll
                for (int jj = 0; jj < 8; jj++) acc[ii][jj] += a[ii] * b[jj];
        }
        __syncthreads();
    }

#pragma unroll
    for (int ii = 0; ii < 8; ii++) {
        int m = m0 + ty * 8 + ii;
        if (m < VOCAB) {
            float4 v0 = make_float4(acc[ii][0], acc[ii][1], acc[ii][2], acc[ii][3]);
            float4 v1 = make_float4(acc[ii][4], acc[ii][5], acc[ii][6], acc[ii][7]);
            *(float4*)(g_proj + (size_t)m * HDIM + n0 + tx * 8)     = v0;
            *(float4*)(g_proj + (size_t)m * HDIM + n0 + tx * 8 + 4) = v1;
        }
    }
}

// ---------------------------------------------------------------------------
// Kernel B: RNN scan. 64 clusters x 2 CTAs of 1024 threads.
// Warp-specialized: warps 0-15 (A) consume the locally-produced h-half,
// warps 16-31 (B) consume the remote half + run the serial tail.
// A -> B handoff: named bar 1 (arrive/sync). B -> A handoff: named bar 2.
// Cross-CTA: st.shared::cluster + one barrier.cluster arrive/wait per step.
// No __syncthreads in the loop.
// ---------------------------------------------------------------------------
__device__ __forceinline__ void fma2(u64& acc, u64 a, u64 b) {
    asm("fma.rn.f32x2 %0, %1, %2, %0;" : "+l"(acc) : "l"(a), "l"(b));
}
__device__ __forceinline__ u64 add2(u64 a, u64 b) {
    u64 r;
    asm("add.rn.f32x2 %0, %1, %2;" : "=l"(r) : "l"(a), "l"(b));
    return r;
}
__device__ __forceinline__ uint32_t s2u(const void* p) {
    return (uint32_t)__cvta_generic_to_shared(p);
}
__device__ __forceinline__ uint32_t mapa_u32(uint32_t a, uint32_t r) {
    uint32_t ret;
    asm("mapa.shared::cluster.u32 %0, %1, %2;" : "=r"(ret) : "r"(a), "r"(r));
    return ret;
}
__device__ __forceinline__ void st_remote_f32(uint32_t ra, float v) {
    asm volatile("st.shared::cluster.f32 [%0], %1;" :: "r"(ra), "f"(v) : "memory");
}
__device__ __forceinline__ void bar_arrive(int b, int cnt) {
    asm volatile("bar.arrive %0, %1;" :: "r"(b), "r"(cnt) : "memory");
}
__device__ __forceinline__ void bar_sync(int b, int cnt) {
    asm volatile("bar.sync %0, %1;" :: "r"(b), "r"(cnt) : "memory");
}
__device__ __forceinline__ void cl_arrive() {
    asm volatile("barrier.cluster.arrive.aligned;" ::: "memory");
}
__device__ __forceinline__ void cl_wait() {
    asm volatile("barrier.cluster.wait.aligned;" ::: "memory");
}
// exact-enough tanh: err ~1e-7, ~8 instrs (vs ~20+ for tanhf)
__device__ __forceinline__ float fast_tanh(float x) {
    float xc = fminf(fmaxf(x, -15.0f), 15.0f);
    float e  = __expf(2.0f * xc);
    return __fdividef(e - 1.0f, e + 1.0f);
}

__global__ void __cluster_dims__(2, 1, 1) __launch_bounds__(1024, 1)
scan_kernel(const int* __restrict__ reviews, const int* __restrict__ lengths,
            const float* __restrict__ Whh, const float* __restrict__ Wcls,
            const float* __restrict__ bcls, float* __restrict__ out) {
    __shared__ __align__(16) float hbuf[2][HDIM];
    __shared__ float ps[128];
    __shared__ int toks[TLEN];

    const int tid  = threadIdx.x;
    const int w    = tid >> 5;
    const int l    = tid & 31;
    const bool isB = (w >= 16);
    const int wl   = w & 15;
    const int i    = wl * 8 + (l >> 2);     // output index 0..127
    const int s    = l & 3;                 // K-slice (interleaved float4 blocks)
    const int b    = blockIdx.x >> 1;
    const int rank = blockIdx.x & 1;
    const int peer = rank ^ 1;
    const int len  = lengths[b];
    const int ownK  = rank * 128;           // h range produced locally
    const int peerK = 128 - ownK;

    for (int idx = tid; idx < TLEN; idx += 1024)
        toks[idx] = reviews[b * TLEN + idx];
    if (tid < HDIM) hbuf[0][tid] = 0.0f;

    // weights: row ownK+i; A covers local half (cols ownK+..), B remote half
    u64 wreg[16];
    {
        const float* wr = Whh + (size_t)(ownK + i) * HDIM + (isB ? peerK : ownK);
#pragma unroll
        for (int m = 0; m < 8; m++) {
            ulonglong2 a = *(const ulonglong2*)(wr + (4 * m + s) * 4);
            wreg[2 * m]     = a.x;
            wreg[2 * m + 1] = a.y;
        }
    }
    __syncthreads();

    const uint32_t rH0 = mapa_u32(s2u(&hbuf[0][ownK + i]), peer);
    const uint32_t rH1 = mapa_u32(s2u(&hbuf[1][ownK + i]), peer);

    cl_arrive();                            // arm cluster phase 0

    if (!isB) {
        // -------- producer group A: local-half partials --------
        bar_sync(2, 1024);                  // consumes B's prologue arrive? no:
        // B hasn't arrived b2 yet -> first iteration must not wait. Use loop
        // structure where the t=0 sync is satisfied by a prologue arrive:
        // (handled below: B arrives b2 in prologue BEFORE cl_arrive? No --
        //  simplest: A's first b2 sync pairs with B's prologue arrive issued
        //  right after __syncthreads above. See B path.)
        for (int t = 0; t < len; ++t) {
            const float* hb = hbuf[t & 1] + ownK;
            u64 a0 = 0ull, a1 = 0ull, a2 = 0ull, a3 = 0ull;
#pragma unroll
            for (int m = 0; m < 8; m += 2) {
                ulonglong2 h0 = *(const ulonglong2*)(hb + (4 * m + s) * 4);
                ulonglong2 h1 = *(const ulonglong2*)(hb + (4 * (m + 1) + s) * 4);
                fma2(a0, wreg[2 * m],     h0.x);
                fma2(a1, wreg[2 * m + 1], h0.y);
                fma2(a2, wreg[2 * m + 2], h1.x);
                fma2(a3, wreg[2 * m + 3], h1.y);
            }
            u64 aa = add2(add2(a0, a1), add2(a2, a3));
            float2 af = *(float2*)&aa;
            float sum = af.x + af.y;
            sum += __shfl_xor_sync(0xffffffffu, sum, 1);
            sum += __shfl_xor_sync(0xffffffffu, sum, 2);
            if (s == 0) ps[i] = sum;
            bar_arrive(1, 1024);            // ps ready for B
            cl_wait();                      // phase t complete (off critical path)
            cl_arrive();                    // contribute to phase t+1
            if (t + 1 < len) bar_sync(2, 1024);  // wait for B's local h store
        }
        cl_wait();                          // final phase: all remote stores visible
        bar_sync(2, 1024);                  // consume B's final b2 arrive
    } else {
        // -------- consumer group B: remote-half partials + serial tail --------
        bar_arrive(2, 1024);                // prologue: h0 ready (synced above)
        float xp_cur = __ldg(g_proj + (size_t)toks[0] * HDIM + ownK + i);
        for (int t = 0; t < len; ++t) {
            cl_wait();                      // phase t: peer's remote h stores visible
            const int p = t & 1, pn = p ^ 1;
            int tn = (t + 1 < len) ? (t + 1) : t;
            float xp_next = __ldg(g_proj + (size_t)toks[tn] * HDIM + ownK + i);

            const float* hb = hbuf[p] + peerK;
            u64 a0 = 0ull, a1 = 0ull, a2 = 0ull, a3 = 0ull;
#pragma unroll
            for (int m = 0; m < 8; m += 2) {
                ulonglong2 h0 = *(const ulonglong2*)(hb + (4 * m + s) * 4);
                ulonglong2 h1 = *(const ulonglong2*)(hb + (4 * (m + 1) + s) * 4);
                fma2(a0, wreg[2 * m],     h0.x);
                fma2(a1, wreg[2 * m + 1], h0.y);
                fma2(a2, wreg[2 * m + 2], h1.x);
                fma2(a3, wreg[2 * m + 3], h1.y);
            }
            u64 aa = add2(add2(a0, a1), add2(a2, a3));
            float2 af = *(float2*)&aa;
            float sum = af.x + af.y;
            sum += __shfl_xor_sync(0xffffffffu, sum, 1);
            sum += __shfl_xor_sync(0xffffffffu, sum, 2);

            bar_sync(1, 1024);              // A's ps ready (usually pre-satisfied)
            float v = fast_tanh(sum + ps[i] + xp_cur);
            if (s == 0) {
                hbuf[pn][ownK + i] = v;                 // local copy
                st_remote_f32(pn ? rH1 : rH0, v);       // peer copy (DSMEM)
            }
            bar_arrive(2, 1024);            // local h ready for A
            cl_arrive();                    // phase t+1: releases remote stores
            xp_cur = xp_next;
        }
        cl_wait();                          // final phase
    }

    // classifier: rank 0, warps 0-1 (group A — ordered by cl_wait + bar_sync(2))
    if (rank == 0 && tid < 64) {
        int c = tid >> 5, lane = tid & 31;
        const float* hf = hbuf[len & 1];
        float sum = 0.0f;
#pragma unroll
        for (int m = 0; m < 8; m++)
            sum += Wcls[c * HDIM + lane + 32 * m] * hf[lane + 32 * m];
#pragma unroll
        for (int o = 16; o > 0; o >>= 1) sum += __shfl_down_sync(0xffffffffu, sum, o);
        if (lane == 0) out[b * 2 + c] = sum + bcls[c];
    }
}

// ---------------------------------------------------------------------------
extern "C" void kernel_launch(void* const* d_in, const int* in_sizes, int n_in,
                              void* d_out, int out_size) {
    const int*   reviews = (const int*)d_in[0];
    const int*   lengths = (const int*)d_in[1];
    const float* emb     = (const float*)d_in[2];
    const float* Wih     = (const float*)d_in[3];
    const float* Whh     = (const float*)d_in[4];
    const float* Wcls    = (const float*)d_in[5];
    const float* bcls    = (const float*)d_in[6];
    float*       out     = (float*)d_out;

    dim3 gA(2, (VOCAB + 127) / 128);
    proj_kernel<<<gA, 256>>>(emb, Wih);

    scan_kernel<<<BATCH * 2, 1024>>>(reviews, lengths, Whh, Wcls, bcls, out);
}